// round 10
// baseline (speedup 1.0000x reference)
#include <cuda_runtime.h>
#include <cuda_bf16.h>

// LightGCNConv R10: R7 pipeline (measured 47.9us best) with gather unroll 8
// for deeper load batching (fewer exposed L2-latency waits per node).
//
// Pipeline (4 launches, no memset):
//  1) zero: outdeg/cursor/ovf_count = 0
//  2) bin: one edge/thread; outdeg RED; slot=atomicAdd(cursor[dst]);
//     bucket[dst*CAP+slot]=src; overflow (deg>CAP, ~never) -> pair list
//  3) norm: nsrc=rsqrt(max(outdeg,1)), ndst=rsqrt(max(cursor,1))
//  4) gather: 16 lanes/node, reg accumulate, one write per output element

#define MAX_NODES 100000
#define DFEAT 64
#define DVEC 16   // float4s per row
#define CAP 32    // bucket row = 128B line; P(deg>32) ~ 4e-9
#define OVF_MAX 4096

__device__ int   g_outdeg[MAX_NODES];
__device__ int   g_cursor[MAX_NODES];          // becomes in-degree
__device__ float g_nsrc[MAX_NODES];
__device__ float g_ndst[MAX_NODES];
__device__ int   g_bucket[MAX_NODES * CAP];    // 12.8 MB scratch
__device__ int   g_ovf_src[OVF_MAX];
__device__ int   g_ovf_dst[OVF_MAX];
__device__ int   g_ovf_count;

__global__ void zero_kernel(int n) {
    int i = blockIdx.x * blockDim.x + threadIdx.x;
    if (i < n) {
        g_outdeg[i] = 0;
        g_cursor[i] = 0;
    }
    if (i == 0) g_ovf_count = 0;
}

__global__ void bin_kernel(const int* __restrict__ src,
                           const int* __restrict__ dst, int E) {
    int e = blockIdx.x * blockDim.x + threadIdx.x;
    if (e >= E) return;
    int s = src[e];
    int d = dst[e];
    atomicAdd(&g_outdeg[s], 1);                // result unused -> RED
    int slot = atomicAdd(&g_cursor[d], 1);
    if (slot < CAP) {
        g_bucket[d * CAP + slot] = s;
    } else {
        int pos = atomicAdd(&g_ovf_count, 1);
        if (pos < OVF_MAX) {
            g_ovf_src[pos] = s;
            g_ovf_dst[pos] = d;
        }
    }
}

__global__ void norm_kernel(int n) {
    int i = blockIdx.x * blockDim.x + threadIdx.x;
    if (i < n) {
        g_nsrc[i] = rsqrtf((float)max(g_outdeg[i], 1));
        g_ndst[i] = rsqrtf((float)max(g_cursor[i], 1));
    }
}

// 16 lanes per node; lane q owns float4 #q. No atomics, one write per elem.
__global__ void __launch_bounds__(256)
gather_kernel(const float4* __restrict__ feat,
              float4* __restrict__ out, int N) {
    int t = blockIdx.x * blockDim.x + threadIdx.x;
    int node = t >> 4;
    int q = t & 15;
    if (node >= N) return;

    int deg = __ldg(&g_cursor[node]);          // broadcast across the 16 lanes
    int k = min(deg, CAP);

    float4 acc = make_float4(0.f, 0.f, 0.f, 0.f);
    const int* bkt = &g_bucket[node * CAP];

    #pragma unroll 8
    for (int i = 0; i < k; i++) {
        int s = __ldg(&bkt[i]);                // broadcast (single line per node)
        float rn = __ldg(&g_nsrc[s]);          // broadcast
        float4 v = __ldg(&feat[(unsigned)s * DVEC + q]);
        acc.x = fmaf(v.x, rn, acc.x);
        acc.y = fmaf(v.y, rn, acc.y);
        acc.z = fmaf(v.z, rn, acc.z);
        acc.w = fmaf(v.w, rn, acc.w);
    }

    // Slow path: edges that overflowed this node's bucket (expected: none).
    if (deg > CAP) {
        int ovfn = min(g_ovf_count, OVF_MAX);
        for (int j = 0; j < ovfn; j++) {
            if (g_ovf_dst[j] == node) {
                int s = g_ovf_src[j];
                float rn = __ldg(&g_nsrc[s]);
                float4 v = __ldg(&feat[(unsigned)s * DVEC + q]);
                acc.x = fmaf(v.x, rn, acc.x);
                acc.y = fmaf(v.y, rn, acc.y);
                acc.z = fmaf(v.z, rn, acc.z);
                acc.w = fmaf(v.w, rn, acc.w);
            }
        }
    }

    float nd = __ldg(&g_ndst[node]);
    acc.x *= nd; acc.y *= nd; acc.z *= nd; acc.w *= nd;
    out[(long long)node * DVEC + q] = acc;
}

extern "C" void kernel_launch(void* const* d_in, const int* in_sizes, int n_in,
                              void* d_out, int out_size) {
    const float4* feat = (const float4*)d_in[0];
    const int*    src  = (const int*)d_in[1];
    const int*    dst  = (const int*)d_in[2];
    float4*       out  = (float4*)d_out;

    int N = in_sizes[0] / DFEAT;   // 100000
    int E = in_sizes[1];           // 1000000

    // 1) zero scratch
    {
        int threads = 256;
        int blocks = (N + threads - 1) / threads;
        zero_kernel<<<blocks, threads>>>(N);
    }

    // 2) degree count + dst binning
    {
        int threads = 256;
        int blocks = (E + threads - 1) / threads;
        bin_kernel<<<blocks, threads>>>(src, dst, E);
    }

    // 3) per-node norms
    {
        int threads = 256;
        int blocks = (N + threads - 1) / threads;
        norm_kernel<<<blocks, threads>>>(N);
    }

    // 4) register-accumulated gather, single write per output element
    {
        long long total = (long long)N * DVEC;
        int threads = 256;
        int blocks = (int)((total + threads - 1) / threads);
        gather_kernel<<<blocks, threads>>>(feat, out, N);
    }
}

// round 11
// speedup vs baseline: 1.0125x; 1.0125x over previous
#include <cuda_runtime.h>
#include <cuda_bf16.h>

// LightGCNConv R11: R7 pipeline; gather = one WARP per node (kills the
// 2-nodes-per-warp E[max(deg,deg)] imbalance, ~23%), with the R7-proven
// broadcast-LDG loop body (NOT shfl, NOT smem): per iteration
// idx bcast LDG + nsrc bcast LDG + feat LDG.64 + 2 FMA, unroll 4.
//
// Pipeline (4 launches, no memset):
//  1) zero  2) bin (1 edge/thread)  3) norm  4) gather

#define MAX_NODES 100000
#define DFEAT 64
#define F2VEC 32  // float2s per row
#define CAP 32    // bucket row = 128B line; P(deg>32) ~ 4e-9
#define OVF_MAX 4096

__device__ int   g_outdeg[MAX_NODES];
__device__ int   g_cursor[MAX_NODES];          // becomes in-degree
__device__ float g_nsrc[MAX_NODES];
__device__ float g_ndst[MAX_NODES];
__device__ int   g_bucket[MAX_NODES * CAP];    // 12.8 MB scratch
__device__ int   g_ovf_src[OVF_MAX];
__device__ int   g_ovf_dst[OVF_MAX];
__device__ int   g_ovf_count;

__global__ void zero_kernel(int n) {
    int i = blockIdx.x * blockDim.x + threadIdx.x;
    if (i < n) {
        g_outdeg[i] = 0;
        g_cursor[i] = 0;
    }
    if (i == 0) g_ovf_count = 0;
}

__global__ void bin_kernel(const int* __restrict__ src,
                           const int* __restrict__ dst, int E) {
    int e = blockIdx.x * blockDim.x + threadIdx.x;
    if (e >= E) return;
    int s = src[e];
    int d = dst[e];
    atomicAdd(&g_outdeg[s], 1);                // result unused -> RED
    int slot = atomicAdd(&g_cursor[d], 1);
    if (slot < CAP) {
        g_bucket[d * CAP + slot] = s;
    } else {
        int pos = atomicAdd(&g_ovf_count, 1);
        if (pos < OVF_MAX) {
            g_ovf_src[pos] = s;
            g_ovf_dst[pos] = d;
        }
    }
}

__global__ void norm_kernel(int n) {
    int i = blockIdx.x * blockDim.x + threadIdx.x;
    if (i < n) {
        g_nsrc[i] = rsqrtf((float)max(g_outdeg[i], 1));
        g_ndst[i] = rsqrtf((float)max(g_cursor[i], 1));
    }
}

// One warp per node; lane l owns float2 #l of the 64-float row.
// Loop body: 2 broadcast LDGs + 1 feat LDG.64 + 2 FMA (same shape as R7).
__global__ void __launch_bounds__(256)
gather_kernel(const float2* __restrict__ feat2,
              float2* __restrict__ out2, int N) {
    unsigned t = blockIdx.x * blockDim.x + threadIdx.x;
    unsigned node = t >> 5;
    unsigned lane = t & 31u;
    if (node >= (unsigned)N) return;

    int deg = __ldg(&g_cursor[node]);          // broadcast (whole warp, 1 line)
    int k = min(deg, CAP);

    float2 acc = make_float2(0.f, 0.f);
    const int* bkt = &g_bucket[node * CAP];

    #pragma unroll 4
    for (int i = 0; i < k; i++) {
        int s = __ldg(&bkt[i]);                // warp-wide broadcast, 1 wavefront
        float rn = __ldg(&g_nsrc[s]);          // warp-wide broadcast
        float2 v = __ldg(&feat2[(unsigned)s * F2VEC + lane]);
        acc.x = fmaf(v.x, rn, acc.x);
        acc.y = fmaf(v.y, rn, acc.y);
    }

    // Slow path: edges that overflowed this node's bucket (expected: none).
    if (deg > CAP) {
        int ovfn = min(g_ovf_count, OVF_MAX);
        for (int j = 0; j < ovfn; j++) {
            if (g_ovf_dst[j] == (int)node) {
                int s = g_ovf_src[j];
                float rn = __ldg(&g_nsrc[s]);
                float2 v = __ldg(&feat2[(unsigned)s * F2VEC + lane]);
                acc.x = fmaf(v.x, rn, acc.x);
                acc.y = fmaf(v.y, rn, acc.y);
            }
        }
    }

    float nd = __ldg(&g_ndst[node]);
    acc.x *= nd;
    acc.y *= nd;
    out2[(unsigned)node * F2VEC + lane] = acc;
}

extern "C" void kernel_launch(void* const* d_in, const int* in_sizes, int n_in,
                              void* d_out, int out_size) {
    const float2* feat2 = (const float2*)d_in[0];
    const int*    src   = (const int*)d_in[1];
    const int*    dst   = (const int*)d_in[2];
    float2*       out2  = (float2*)d_out;

    int N = in_sizes[0] / DFEAT;   // 100000
    int E = in_sizes[1];           // 1000000

    // 1) zero scratch
    {
        int threads = 256;
        int blocks = (N + threads - 1) / threads;
        zero_kernel<<<blocks, threads>>>(N);
    }

    // 2) degree count + dst binning
    {
        int threads = 256;
        int blocks = (E + threads - 1) / threads;
        bin_kernel<<<blocks, threads>>>(src, dst, E);
    }

    // 3) per-node norms
    {
        int threads = 256;
        int blocks = (N + threads - 1) / threads;
        norm_kernel<<<blocks, threads>>>(N);
    }

    // 4) warp-per-node gather (broadcast-LDG body), one write per element
    {
        long long total = (long long)N * 32;
        int threads = 256;
        int blocks = (int)((total + threads - 1) / threads);
        gather_kernel<<<blocks, threads>>>(feat2, out2, N);
    }
}

// round 12
// speedup vs baseline: 1.0417x; 1.0289x over previous
#include <cuda_runtime.h>
#include <cuda_bf16.h>

// LightGCNConv R12: R7 configuration (measured best 47.9us) with gather/bin
// byte-preserved; zero/norm kernels vectorized (int4/float4, 4 nodes/thread).
//
// Pipeline (4 launches, no memset):
//  1) zero: outdeg/cursor/ovf_count = 0 (int4 stores)
//  2) bin: one edge/thread; outdeg RED; slot=atomicAdd(cursor[dst]);
//     bucket[dst*CAP+slot]=src; overflow (deg>CAP, ~never) -> pair list
//  3) norm: 4 nodes/thread, vectorized rsqrt of clipped degrees
//  4) gather: 16 lanes/node, float4, unroll 4, one write per output element

#define MAX_NODES 100000   // divisible by 4
#define DFEAT 64
#define DVEC 16   // float4s per row
#define CAP 32    // bucket row = 128B line; P(deg>32) ~ 4e-9
#define OVF_MAX 4096

__device__ int   g_outdeg[MAX_NODES];
__device__ int   g_cursor[MAX_NODES];          // becomes in-degree
__device__ float g_nsrc[MAX_NODES];
__device__ float g_ndst[MAX_NODES];
__device__ int   g_bucket[MAX_NODES * CAP];    // 12.8 MB scratch
__device__ int   g_ovf_src[OVF_MAX];
__device__ int   g_ovf_dst[OVF_MAX];
__device__ int   g_ovf_count;

// One thread zeroes 4 outdeg + 4 cursor entries (int4 stores).
__global__ void zero_kernel(int n4) {
    int i = blockIdx.x * blockDim.x + threadIdx.x;
    if (i < n4) {
        ((int4*)g_outdeg)[i] = make_int4(0, 0, 0, 0);
        ((int4*)g_cursor)[i] = make_int4(0, 0, 0, 0);
    }
    if (i == 0) g_ovf_count = 0;
}

__global__ void bin_kernel(const int* __restrict__ src,
                           const int* __restrict__ dst, int E) {
    int e = blockIdx.x * blockDim.x + threadIdx.x;
    if (e >= E) return;
    int s = src[e];
    int d = dst[e];
    atomicAdd(&g_outdeg[s], 1);                // result unused -> RED
    int slot = atomicAdd(&g_cursor[d], 1);
    if (slot < CAP) {
        g_bucket[d * CAP + slot] = s;
    } else {
        int pos = atomicAdd(&g_ovf_count, 1);
        if (pos < OVF_MAX) {
            g_ovf_src[pos] = s;
            g_ovf_dst[pos] = d;
        }
    }
}

// One thread computes 4 nodes' norms (vectorized int4 loads, float4 stores).
__global__ void norm_kernel(int n4) {
    int i = blockIdx.x * blockDim.x + threadIdx.x;
    if (i >= n4) return;
    int4 od = ((const int4*)g_outdeg)[i];
    int4 id = ((const int4*)g_cursor)[i];
    float4 ns, nd;
    ns.x = rsqrtf((float)max(od.x, 1));
    ns.y = rsqrtf((float)max(od.y, 1));
    ns.z = rsqrtf((float)max(od.z, 1));
    ns.w = rsqrtf((float)max(od.w, 1));
    nd.x = rsqrtf((float)max(id.x, 1));
    nd.y = rsqrtf((float)max(id.y, 1));
    nd.z = rsqrtf((float)max(id.z, 1));
    nd.w = rsqrtf((float)max(id.w, 1));
    ((float4*)g_nsrc)[i] = ns;
    ((float4*)g_ndst)[i] = nd;
}

// 16 lanes per node; lane q owns float4 #q. No atomics, one write per elem.
// Byte-identical loop structure to R7 (measured best).
__global__ void gather_kernel(const float4* __restrict__ feat,
                              float4* __restrict__ out, int N) {
    unsigned t = blockIdx.x * blockDim.x + threadIdx.x;
    unsigned node = t >> 4;
    unsigned q = t & 15u;
    if (node >= (unsigned)N) return;

    int deg = __ldg(&g_cursor[node]);          // broadcast across the 16 lanes
    int k = min(deg, CAP);

    float4 acc = make_float4(0.f, 0.f, 0.f, 0.f);
    const int* bkt = &g_bucket[node * CAP];

    #pragma unroll 4
    for (int i = 0; i < k; i++) {
        int s = __ldg(&bkt[i]);                // broadcast (single line per node)
        float rn = __ldg(&g_nsrc[s]);          // broadcast
        float4 v = __ldg(&feat[(unsigned)s * DVEC + q]);
        acc.x = fmaf(v.x, rn, acc.x);
        acc.y = fmaf(v.y, rn, acc.y);
        acc.z = fmaf(v.z, rn, acc.z);
        acc.w = fmaf(v.w, rn, acc.w);
    }

    // Slow path: edges that overflowed this node's bucket (expected: none).
    if (deg > CAP) {
        int ovfn = min(g_ovf_count, OVF_MAX);
        for (int j = 0; j < ovfn; j++) {
            if (g_ovf_dst[j] == (int)node) {
                int s = g_ovf_src[j];
                float rn = __ldg(&g_nsrc[s]);
                float4 v = __ldg(&feat[(unsigned)s * DVEC + q]);
                acc.x = fmaf(v.x, rn, acc.x);
                acc.y = fmaf(v.y, rn, acc.y);
                acc.z = fmaf(v.z, rn, acc.z);
                acc.w = fmaf(v.w, rn, acc.w);
            }
        }
    }

    float nd = __ldg(&g_ndst[node]);
    acc.x *= nd; acc.y *= nd; acc.z *= nd; acc.w *= nd;
    out[node * DVEC + q] = acc;
}

extern "C" void kernel_launch(void* const* d_in, const int* in_sizes, int n_in,
                              void* d_out, int out_size) {
    const float4* feat = (const float4*)d_in[0];
    const int*    src  = (const int*)d_in[1];
    const int*    dst  = (const int*)d_in[2];
    float4*       out  = (float4*)d_out;

    int N = in_sizes[0] / DFEAT;   // 100000
    int E = in_sizes[1];           // 1000000
    int N4 = (N + 3) / 4;          // 25000 (N divisible by 4)

    // 1) zero scratch (vectorized)
    {
        int threads = 256;
        int blocks = (N4 + threads - 1) / threads;
        zero_kernel<<<blocks, threads>>>(N4);
    }

    // 2) degree count + dst binning (byte-identical to R7)
    {
        int threads = 256;
        int blocks = (E + threads - 1) / threads;
        bin_kernel<<<blocks, threads>>>(src, dst, E);
    }

    // 3) per-node norms (vectorized, 4 nodes/thread)
    {
        int threads = 256;
        int blocks = (N4 + threads - 1) / threads;
        norm_kernel<<<blocks, threads>>>(N4);
    }

    // 4) register-accumulated gather, single write per output element
    {
        long long total = (long long)N * DVEC;
        int threads = 256;
        int blocks = (int)((total + threads - 1) / threads);
        gather_kernel<<<blocks, threads>>>(feat, out, N);
    }
}

// round 13
// speedup vs baseline: 1.0914x; 1.0477x over previous
#include <cuda_runtime.h>
#include <cuda_bf16.h>

// LightGCNConv R13: hot kernels (bin, gather) VERBATIM from R7 (measured
// 47.9us best); cold kernels (zero, norm) vectorized 4-nodes-per-thread.
//
// Pipeline (4 launches, no memset):
//  1) zero: outdeg/cursor/ovf_count = 0 (int4 stores)
//  2) bin: one edge/thread; outdeg RED; slot=atomicAdd(cursor[dst]);
//     bucket[dst*CAP+slot]=src; overflow (deg>CAP, ~never) -> pair list
//  3) norm: 4 nodes/thread, vectorized rsqrt of clipped degrees
//  4) gather: 16 lanes/node, float4, unroll 4, one write per output element

#define MAX_NODES 100000   // divisible by 4
#define DFEAT 64
#define DVEC 16   // float4s per row
#define CAP 32    // bucket row = 128B line; P(deg>32) ~ 4e-9
#define OVF_MAX 4096

__device__ int   g_outdeg[MAX_NODES];
__device__ int   g_cursor[MAX_NODES];          // becomes in-degree
__device__ float g_nsrc[MAX_NODES];
__device__ float g_ndst[MAX_NODES];
__device__ int   g_bucket[MAX_NODES * CAP];    // 12.8 MB scratch
__device__ int   g_ovf_src[OVF_MAX];
__device__ int   g_ovf_dst[OVF_MAX];
__device__ int   g_ovf_count;

// One thread zeroes 4 outdeg + 4 cursor entries (int4 stores).
__global__ void zero_kernel(int n4) {
    int i = blockIdx.x * blockDim.x + threadIdx.x;
    if (i < n4) {
        ((int4*)g_outdeg)[i] = make_int4(0, 0, 0, 0);
        ((int4*)g_cursor)[i] = make_int4(0, 0, 0, 0);
    }
    if (i == 0) g_ovf_count = 0;
}

// VERBATIM R7.
__global__ void bin_kernel(const int* __restrict__ src,
                           const int* __restrict__ dst, int E) {
    int e = blockIdx.x * blockDim.x + threadIdx.x;
    if (e >= E) return;
    int s = src[e];
    int d = dst[e];
    atomicAdd(&g_outdeg[s], 1);                // result unused -> RED
    int slot = atomicAdd(&g_cursor[d], 1);
    if (slot < CAP) {
        g_bucket[d * CAP + slot] = s;
    } else {
        int pos = atomicAdd(&g_ovf_count, 1);
        if (pos < OVF_MAX) {
            g_ovf_src[pos] = s;
            g_ovf_dst[pos] = d;
        }
    }
}

// One thread computes 4 nodes' norms (vectorized int4 loads, float4 stores).
__global__ void norm_kernel(int n4) {
    int i = blockIdx.x * blockDim.x + threadIdx.x;
    if (i >= n4) return;
    int4 od = ((const int4*)g_outdeg)[i];
    int4 id = ((const int4*)g_cursor)[i];
    float4 ns, nd;
    ns.x = rsqrtf((float)max(od.x, 1));
    ns.y = rsqrtf((float)max(od.y, 1));
    ns.z = rsqrtf((float)max(od.z, 1));
    ns.w = rsqrtf((float)max(od.w, 1));
    nd.x = rsqrtf((float)max(id.x, 1));
    nd.y = rsqrtf((float)max(id.y, 1));
    nd.z = rsqrtf((float)max(id.z, 1));
    nd.w = rsqrtf((float)max(id.w, 1));
    ((float4*)g_nsrc)[i] = ns;
    ((float4*)g_ndst)[i] = nd;
}

// VERBATIM R7: 16 lanes per node; lane q owns float4 #q.
__global__ void gather_kernel(const float4* __restrict__ feat,
                              float4* __restrict__ out, int N) {
    int t = blockIdx.x * blockDim.x + threadIdx.x;
    int node = t >> 4;
    int q = t & 15;
    if (node >= N) return;

    int deg = __ldg(&g_cursor[node]);          // broadcast across the 16 lanes
    int k = min(deg, CAP);

    float4 acc = make_float4(0.f, 0.f, 0.f, 0.f);
    const int* bkt = &g_bucket[node * CAP];

    #pragma unroll 4
    for (int i = 0; i < k; i++) {
        int s = __ldg(&bkt[i]);                // broadcast (single line per node)
        float rn = __ldg(&g_nsrc[s]);          // broadcast
        float4 v = __ldg(&feat[(long long)s * DVEC + q]);
        acc.x = fmaf(v.x, rn, acc.x);
        acc.y = fmaf(v.y, rn, acc.y);
        acc.z = fmaf(v.z, rn, acc.z);
        acc.w = fmaf(v.w, rn, acc.w);
    }

    // Slow path: edges that overflowed this node's bucket (expected: none).
    if (deg > CAP) {
        int ovfn = min(g_ovf_count, OVF_MAX);
        for (int j = 0; j < ovfn; j++) {
            if (g_ovf_dst[j] == node) {
                int s = g_ovf_src[j];
                float rn = __ldg(&g_nsrc[s]);
                float4 v = __ldg(&feat[(long long)s * DVEC + q]);
                acc.x = fmaf(v.x, rn, acc.x);
                acc.y = fmaf(v.y, rn, acc.y);
                acc.z = fmaf(v.z, rn, acc.z);
                acc.w = fmaf(v.w, rn, acc.w);
            }
        }
    }

    float nd = __ldg(&g_ndst[node]);
    acc.x *= nd; acc.y *= nd; acc.z *= nd; acc.w *= nd;
    out[(long long)node * DVEC + q] = acc;
}

extern "C" void kernel_launch(void* const* d_in, const int* in_sizes, int n_in,
                              void* d_out, int out_size) {
    const float4* feat = (const float4*)d_in[0];
    const int*    src  = (const int*)d_in[1];
    const int*    dst  = (const int*)d_in[2];
    float4*       out  = (float4*)d_out;

    int N = in_sizes[0] / DFEAT;   // 100000
    int E = in_sizes[1];           // 1000000
    int N4 = (N + 3) / 4;          // 25000

    // 1) zero scratch (vectorized)
    {
        int threads = 256;
        int blocks = (N4 + threads - 1) / threads;
        zero_kernel<<<blocks, threads>>>(N4);
    }

    // 2) degree count + dst binning (verbatim R7)
    {
        int threads = 256;
        int blocks = (E + threads - 1) / threads;
        bin_kernel<<<blocks, threads>>>(src, dst, E);
    }

    // 3) per-node norms (vectorized, 4 nodes/thread)
    {
        int threads = 256;
        int blocks = (N4 + threads - 1) / threads;
        norm_kernel<<<blocks, threads>>>(N4);
    }

    // 4) register-accumulated gather, single write per output element (verbatim R7)
    {
        long long total = (long long)N * DVEC;
        int threads = 256;
        int blocks = (int)((total + threads - 1) / threads);
        gather_kernel<<<blocks, threads>>>(feat, out, N);
    }
}